// round 4
// baseline (speedup 1.0000x reference)
#include <cuda_runtime.h>
#include <cstddef>

#define NA 192
#define TT 80
#define NC 5
#define TILE 32
#define NTHREADS 256
#define NPAIRS 21
#define BIGF 3.4e38f

typedef unsigned long long u64;

__device__ __forceinline__ u64 pk(float lo, float hi) {
    u64 r; asm("mov.b64 %0, {%1,%2};" : "=l"(r) : "f"(lo), "f"(hi)); return r;
}
__device__ __forceinline__ void upk(float& lo, float& hi, u64 v) {
    asm("mov.b64 {%0,%1}, %2;" : "=f"(lo), "=f"(hi) : "l"(v));
}
__device__ __forceinline__ u64 fma2(u64 a, u64 b, u64 c) {
    u64 d; asm("fma.rn.f32x2 %0,%1,%2,%3;" : "=l"(d) : "l"(a), "l"(b), "l"(c)); return d;
}
__device__ __forceinline__ u64 add2(u64 a, u64 b) {
    u64 d; asm("add.rn.f32x2 %0,%1,%2;" : "=l"(d) : "l"(a), "l"(b)); return d;
}
__device__ __forceinline__ u64 mul2(u64 a, u64 b) {
    u64 d; asm("mul.rn.f32x2 %0,%1,%2;" : "=l"(d) : "l"(a), "l"(b)); return d;
}

__constant__ unsigned char cIT[NPAIRS] = {0,0,0,0,0,0,1,1,1,1,1,2,2,2,2,3,3,3,4,4,5};
__constant__ unsigned char cJT[NPAIRS] = {0,1,2,3,4,5,1,2,3,4,5,2,3,4,5,3,4,5,4,5,5};

__global__ __launch_bounds__(NTHREADS) void veh_coll_kernel(
    const float* __restrict__ traj,        // (NA, T, 4)
    const float* __restrict__ centroids,   // (NA, NC, 4)
    const float* __restrict__ pen,         // (NA, NA)
    float* __restrict__ out,               // [pen (T,NA,NA)][mask (T,NA,NA)]
    int write_mask)
{
    __shared__ float4 sPose[2 * TILE];          // [0,32) = I side, [32,64) = J side
    __shared__ float  sS[2 * TILE][8];          // s0..s4 (+pad), 16B-aligned rows
    __shared__ float  sTile[TILE][TILE + 4];    // pv, padded for float4 + transpose

    const int t   = blockIdx.x;
    const int pr  = blockIdx.y;
    const int it  = cIT[pr];
    const int jt  = cJT[pr];
    const int tid = threadIdx.x;

    // ---- Stage poses + s values for both tiles ----
    if (tid < 2 * TILE) {
        int side = tid >> 5, loc = tid & 31;
        int a = (side ? jt : it) * TILE + loc;
        float4 tr = *reinterpret_cast<const float4*>(traj + (a * TT + t) * 4);
        float inv = rsqrtf(tr.z * tr.z + tr.w * tr.w);
        sPose[tid] = make_float4(tr.x, tr.y, tr.z * inv, tr.w * inv);
    }
    for (int p = tid; p < 2 * TILE * NC; p += NTHREADS) {
        int q = p / NC;
        int c = p - q * NC;
        int side = q >> 5, loc = q & 31;
        int a = (side ? jt : it) * TILE + loc;
        sS[q][c] = centroids[(a * NC + c) * 4];
    }
    __syncthreads();

    // ---- Thread layout: iq = i local (0..31), 4 adjacent j per thread ----
    const int iq  = tid >> 3;
    const int jb  = (tid & 7) * 4;          // j local base
    const int ig  = it * TILE + iq;
    const int jgb = jt * TILE + jb;

    const float4 pi = sPose[iq];
    float si[NC], st[NC], s2[NC];
    #pragma unroll
    for (int c = 0; c < NC; c++) {
        si[c] = sS[iq][c];
        st[c] = si[c] + si[c];
        s2[c] = si[c] * si[c];
    }

    float mres[4];

    #pragma unroll
    for (int jp = 0; jp < 2; jp++) {
        const int jl0 = jb + 2 * jp;
        float4 pj0 = sPose[TILE + jl0];
        float4 pj1 = sPose[TILE + jl0 + 1];

        // per-j scalars
        float dx0 = pi.x - pj0.x, dy0 = pi.y - pj0.y;
        float dx1 = pi.x - pj1.x, dy1 = pi.y - pj1.y;
        float aa0 = fmaf(dy0, pi.w, dx0 * pi.z);
        float aa1 = fmaf(dy1, pi.w, dx1 * pi.z);
        float bb0 = fmaf(dy0, pj0.w, dx0 * pj0.z);
        float bb1 = fmaf(dy1, pj1.w, dx1 * pj1.z);
        float gg0 = fmaf(pi.w, pj0.w, pi.z * pj0.z);
        float gg1 = fmaf(pi.w, pj1.w, pi.z * pj1.z);
        float BB0 = fmaf(dy0, dy0, dx0 * dx0);
        float BB1 = fmaf(dy1, dy1, dx1 * dx1);

        u64 aaP  = pk(aa0, aa1);
        u64 ngP  = pk(-(gg0 + gg0), -(gg1 + gg1));   // -2g
        u64 nbP  = pk(-(bb0 + bb0), -(bb1 + bb1));   // -2b
        u64 BBP  = pk(BB0, BB1);

        u64 sjP[NC], vP[NC];
        #pragma unroll
        for (int d = 0; d < NC; d++) {
            sjP[d] = pk(sS[TILE + jl0][d], sS[TILE + jl0 + 1][d]);
            vP[d]  = fma2(sjP[d], add2(sjP[d], nbP), BBP);  // B + s_d^2 - 2b s_d
        }

        float m0 = BIGF, m1 = BIGF;
        #pragma unroll
        for (int c = 0; c < NC; c++) {
            u64 scP = pk(si[c], si[c]);
            u64 uP  = fma2(aaP, pk(st[c], st[c]), pk(s2[c], s2[c])); // s_c^2 + 2a s_c
            u64 nkP = mul2(ngP, scP);                                // -2g s_c
            float l0, l1, t0, t1;
            u64 d2 = fma2(nkP, sjP[0], vP[0]);
            upk(l0, l1, d2);
            #pragma unroll
            for (int d = 1; d < NC; d++) {
                d2 = fma2(nkP, sjP[d], vP[d]);
                upk(t0, t1, d2);
                l0 = fminf(l0, t0);
                l1 = fminf(l1, t1);
            }
            u64 mcP = add2(pk(l0, l1), uP);
            upk(t0, t1, mcP);
            m0 = fminf(m0, t0);
            m1 = fminf(m1, t1);
        }
        mres[2 * jp]     = m0;
        mres[2 * jp + 1] = m1;
    }

    // ---- Epilogue: penalties + mask, float4 stores ----
    const float4 pd4 = *reinterpret_cast<const float4*>(pen + ig * NA + jgb);
    float4 pv4;
    pv4.x = 1.0f - __fdividef(sqrtf(fmaxf(mres[0], 0.0f)), pd4.x);
    pv4.y = 1.0f - __fdividef(sqrtf(fmaxf(mres[1], 0.0f)), pd4.y);
    pv4.z = 1.0f - __fdividef(sqrtf(fmaxf(mres[2], 0.0f)), pd4.z);
    pv4.w = 1.0f - __fdividef(sqrtf(fmaxf(mres[3], 0.0f)), pd4.w);

    const unsigned P = (unsigned)TT * NA * NA;
    const unsigned idx = ((unsigned)t * NA + ig) * NA + jgb;
    *reinterpret_cast<float4*>(out + idx) = pv4;
    if (write_mask) {
        float4 mk;
        mk.x = (pv4.x >= 0.0f && ig != jgb + 0) ? 1.0f : 0.0f;
        mk.y = (pv4.y >= 0.0f && ig != jgb + 1) ? 1.0f : 0.0f;
        mk.z = (pv4.z >= 0.0f && ig != jgb + 2) ? 1.0f : 0.0f;
        mk.w = (pv4.w >= 0.0f && ig != jgb + 3) ? 1.0f : 0.0f;
        *reinterpret_cast<float4*>(out + P + idx) = mk;
    }
    *reinterpret_cast<float4*>(&sTile[iq][jb]) = pv4;

    // ---- Transposed write for off-diagonal tile pairs ----
    if (it != jt) {
        __syncthreads();
        const int jj  = tid >> 3;            // row of transposed tile (j)
        const int ii0 = (tid & 7) * 4;       // 4 i's per thread
        float4 pv;
        pv.x = sTile[ii0 + 0][jj];
        pv.y = sTile[ii0 + 1][jj];
        pv.z = sTile[ii0 + 2][jj];
        pv.w = sTile[ii0 + 3][jj];
        const unsigned idxT = ((unsigned)t * NA + jt * TILE + jj) * NA + it * TILE + ii0;
        *reinterpret_cast<float4*>(out + idxT) = pv;
        if (write_mask) {
            float4 mk;
            mk.x = (pv.x >= 0.0f) ? 1.0f : 0.0f;
            mk.y = (pv.y >= 0.0f) ? 1.0f : 0.0f;
            mk.z = (pv.z >= 0.0f) ? 1.0f : 0.0f;
            mk.w = (pv.w >= 0.0f) ? 1.0f : 0.0f;
            *reinterpret_cast<float4*>(out + P + idxT) = mk;
        }
    }
}

extern "C" void kernel_launch(void* const* d_in, const int* in_sizes, int n_in,
                              void* d_out, int out_size) {
    const float* traj      = (const float*)d_in[0];
    const float* centroids = (const float*)d_in[1];
    const float* pen       = (const float*)d_in[2];
    // d_in[3] = off_diag_mask (~eye) — recomputed as (i != j) on device.

    float* out = (float*)d_out;
    const size_t P = (size_t)TT * NA * NA;
    int write_mask = ((size_t)out_size >= 2 * P) ? 1 : 0;

    dim3 grid(TT, NPAIRS);   // (80, 21) = 1680 blocks
    veh_coll_kernel<<<grid, NTHREADS>>>(traj, centroids, pen, out, write_mask);
}

// round 6
// speedup vs baseline: 1.2434x; 1.2434x over previous
#include <cuda_runtime.h>
#include <cstddef>

#define NA 192
#define TT 80
#define NC 5
#define TILE 32
#define NTHREADS 256
#define NPAIRS 21
#define BIGF 3.4e38f

__constant__ unsigned char cIT[NPAIRS] = {0,0,0,0,0,0,1,1,1,1,1,2,2,2,2,3,3,3,4,4,5};
__constant__ unsigned char cJT[NPAIRS] = {0,1,2,3,4,5,1,2,3,4,5,2,3,4,5,3,4,5,4,5,5};

__global__ __launch_bounds__(NTHREADS) void veh_coll_kernel(
    const float* __restrict__ traj,        // (NA, T, 4)
    const float* __restrict__ centroids,   // (NA, NC, 4)
    const float* __restrict__ pen,         // (NA, NA)
    float* __restrict__ out,               // [pen (T,NA,NA)][mask (T,NA,NA)]
    int write_mask)
{
    __shared__ float4 sPose[2 * TILE];          // [0,32) = I side, [32,64) = J side
    __shared__ float  sSc[2][NC][TILE];         // s values, [side][circle][agent]
    __shared__ float  sTile[TILE][TILE + 1];    // pv staged for transpose

    const int t   = blockIdx.x;
    const int pr  = blockIdx.y;
    const int it  = cIT[pr];
    const int jt  = cJT[pr];
    const int tid = threadIdx.x;

    // ---- Stage poses (normalized heading) ----
    if (tid < 2 * TILE) {
        int side = tid >> 5, loc = tid & 31;
        int a = (side ? jt : it) * TILE + loc;
        float4 tr = *reinterpret_cast<const float4*>(traj + (a * TT + t) * 4);
        float inv = rsqrtf(tr.z * tr.z + tr.w * tr.w);
        sPose[tid] = make_float4(tr.x, tr.y, tr.z * inv, tr.w * inv);
    }
    // ---- Stage s values (centroid x; cy == 0 by construction) ----
    for (int p = tid; p < 2 * TILE * NC; p += NTHREADS) {
        int q = p / NC;                 // agent slot 0..63
        int c = p - q * NC;
        int side = q >> 5, loc = q & 31;
        int a = (side ? jt : it) * TILE + loc;
        sSc[side][c][loc] = centroids[(a * NC + c) * 4];
    }
    __syncthreads();

    // ---- Thread layout: 1 i (iq), 4 adjacent j (jb..jb+3) ----
    const int iq  = tid >> 3;
    const int jb  = (tid & 7) * 4;
    const int ig  = it * TILE + iq;
    const int jgb = jt * TILE + jb;

    const float4 pi = sPose[iq];
    float si[NC];
    #pragma unroll
    for (int c = 0; c < NC; c++) si[c] = sSc[0][c][iq];   // broadcast

    float mres[4];

    #pragma unroll
    for (int jo = 0; jo < 4; jo++) {
        const int jl = jb + jo;
        const float4 pj = sPose[TILE + jl];

        float dx = pi.x - pj.x;
        float dy = pi.y - pj.y;
        float a  = fmaf(dy, pi.w, dx * pi.z);       // base . h_i
        float b  = fmaf(dy, pj.w, dx * pj.z);       // base . h_j
        float g  = fmaf(pi.w, pj.w, pi.z * pj.z);   // h_i . h_j
        float B  = fmaf(dy, dy, dx * dx);
        float a2 = a + a, b2 = b + b, ng2 = -(g + g);

        float sjv[NC], v[NC];
        #pragma unroll
        for (int d = 0; d < NC; d++) {
            sjv[d] = sSc[1][d][jl];                 // stride-1, conflict-free
            v[d]   = fmaf(sjv[d], sjv[d] - b2, B);  // B + s_d^2 - 2 b s_d
        }

        float m = BIGF;
        #pragma unroll
        for (int c = 0; c < NC; c++) {
            float u = si[c] * (si[c] + a2);          // s_c^2 + 2 a s_c
            float nk = ng2 * si[c];                  // -2 g s_c
            float t0 = fmaf(nk, sjv[0], v[0]);
            float t1 = fmaf(nk, sjv[1], v[1]);
            float t2 = fmaf(nk, sjv[2], v[2]);
            float t3 = fmaf(nk, sjv[3], v[3]);
            float t4 = fmaf(nk, sjv[4], v[4]);
            float m01 = fminf(t0, t1);
            float m23 = fminf(t2, t3);
            float mc  = fminf(fminf(m01, m23), t4);
            m = fminf(m, mc + u);
        }
        mres[jo] = m;
    }

    // ---- Epilogue: vectorized penalty + mask stores ----
    const float4 pd4 = *reinterpret_cast<const float4*>(pen + ig * NA + jgb);
    float4 pv4;
    pv4.x = 1.0f - __fdividef(sqrtf(fmaxf(mres[0], 0.0f)), pd4.x);
    pv4.y = 1.0f - __fdividef(sqrtf(fmaxf(mres[1], 0.0f)), pd4.y);
    pv4.z = 1.0f - __fdividef(sqrtf(fmaxf(mres[2], 0.0f)), pd4.z);
    pv4.w = 1.0f - __fdividef(sqrtf(fmaxf(mres[3], 0.0f)), pd4.w);

    const unsigned P = (unsigned)TT * NA * NA;
    const unsigned idx = ((unsigned)t * NA + ig) * NA + jgb;
    *reinterpret_cast<float4*>(out + idx) = pv4;
    if (write_mask) {
        float4 mk;
        mk.x = (pv4.x >= 0.0f && ig != jgb + 0) ? 1.0f : 0.0f;
        mk.y = (pv4.y >= 0.0f && ig != jgb + 1) ? 1.0f : 0.0f;
        mk.z = (pv4.z >= 0.0f && ig != jgb + 2) ? 1.0f : 0.0f;
        mk.w = (pv4.w >= 0.0f && ig != jgb + 3) ? 1.0f : 0.0f;
        *reinterpret_cast<float4*>(out + P + idx) = mk;
    }
    sTile[iq][jb + 0] = pv4.x;
    sTile[iq][jb + 1] = pv4.y;
    sTile[iq][jb + 2] = pv4.z;
    sTile[iq][jb + 3] = pv4.w;

    // ---- Transposed write for off-diagonal tile pairs ----
    if (it != jt) {
        __syncthreads();
        const int jj  = tid >> 3;            // row of transposed tile (j index)
        const int ii0 = (tid & 7) * 4;       // 4 i's gathered per thread
        float4 pv;
        pv.x = sTile[ii0 + 0][jj];           // (4k + r + jj) mod 32 all-distinct
        pv.y = sTile[ii0 + 1][jj];
        pv.z = sTile[ii0 + 2][jj];
        pv.w = sTile[ii0 + 3][jj];
        const unsigned idxT = ((unsigned)t * NA + jt * TILE + jj) * NA + it * TILE + ii0;
        *reinterpret_cast<float4*>(out + idxT) = pv;
        if (write_mask) {
            float4 mk;
            mk.x = (pv.x >= 0.0f) ? 1.0f : 0.0f;
            mk.y = (pv.y >= 0.0f) ? 1.0f : 0.0f;
            mk.z = (pv.z >= 0.0f) ? 1.0f : 0.0f;
            mk.w = (pv.w >= 0.0f) ? 1.0f : 0.0f;
            *reinterpret_cast<float4*>(out + P + idxT) = mk;  // it!=jt -> off-diagonal
        }
    }
}

extern "C" void kernel_launch(void* const* d_in, const int* in_sizes, int n_in,
                              void* d_out, int out_size) {
    const float* traj      = (const float*)d_in[0];
    const float* centroids = (const float*)d_in[1];
    const float* pen       = (const float*)d_in[2];
    // d_in[3] = off_diag_mask (~eye) — recomputed as (i != j) on device.

    float* out = (float*)d_out;
    const size_t P = (size_t)TT * NA * NA;
    int write_mask = ((size_t)out_size >= 2 * P) ? 1 : 0;

    dim3 grid(TT, NPAIRS);   // (80, 21) = 1680 blocks
    veh_coll_kernel<<<grid, NTHREADS>>>(traj, centroids, pen, out, write_mask);
}

// round 10
// speedup vs baseline: 1.4341x; 1.1533x over previous
#include <cuda_runtime.h>
#include <cstddef>

#define NA 192
#define TT 80
#define NC 5
#define TILE 32
#define NTHREADS 256
#define NPAIRS 21
#define MAGIC 12582912.0f   // 1.5 * 2^23: adds/subtracts to round-to-nearest-int

__constant__ unsigned char cIT[NPAIRS] = {0,0,0,0,0,0,1,1,1,1,1,2,2,2,2,3,3,3,4,4,5};
__constant__ unsigned char cJT[NPAIRS] = {0,1,2,3,4,5,1,2,3,4,5,2,3,4,5,3,4,5,4,5,5};

__global__ __launch_bounds__(NTHREADS) void veh_coll_kernel(
    const float* __restrict__ traj,        // (NA, T, 4)
    const float* __restrict__ centroids,   // (NA, NC, 4)
    const float* __restrict__ pen,         // (NA, NA)
    float* __restrict__ out,               // [pen (T,NA,NA)][mask (T,NA,NA)]
    int write_mask)
{
    __shared__ float4 sPose[2 * TILE];        // [0,32) = I side, [32,64) = J side
    __shared__ float  sG0[2 * TILE];          // s_0 (first circle offset)
    __shared__ float  sGd[2 * TILE];          // delta (grid spacing)
    __shared__ float  sGi[2 * TILE];          // 1/delta
    __shared__ float  sTile[TILE][TILE + 1];  // pv staged for transpose

    const int t   = blockIdx.x;
    const int pr  = blockIdx.y;
    const int it  = cIT[pr];
    const int jt  = cJT[pr];
    const int tid = threadIdx.x;

    // ---- Stage per-agent pose + uniform circle-grid parameters ----
    if (tid < 2 * TILE) {
        int side = tid >> 5, loc = tid & 31;
        int a = (side ? jt : it) * TILE + loc;
        float4 tr = *reinterpret_cast<const float4*>(traj + (a * TT + t) * 4);
        float inv = rsqrtf(tr.z * tr.z + tr.w * tr.w);
        sPose[tid] = make_float4(tr.x, tr.y, tr.z * inv, tr.w * inv);
        float s0 = centroids[(a * NC + 0) * 4];
        float s4 = centroids[(a * NC + 4) * 4];
        float dd = (s4 - s0) * 0.25f;          // uniform spacing (linspace frac)
        sG0[tid] = s0;
        sGd[tid] = dd;
        sGi[tid] = __frcp_rn(dd);
    }
    __syncthreads();

    // ---- lane = j local; each warp walks 4 i's ----
    const int jl   = tid & 31;
    const int warp = tid >> 5;
    const int jg   = jt * TILE + jl;

    const float4 pj   = sPose[TILE + jl];
    const float  sj0  = sG0[TILE + jl];
    const float  dj   = sGd[TILE + jl];
    const float  idj  = sGi[TILE + jl];
    const float  offj = -sj0 * idj;

    const unsigned P = (unsigned)TT * NA * NA;

    #pragma unroll
    for (int w = 0; w < TILE / (NTHREADS / 32); ++w) {
        const int il = warp + w * (NTHREADS / 32);
        const int ig = it * TILE + il;

        const float4 pi = sPose[il];           // broadcast
        const float si0 = sG0[il];
        const float di  = sGd[il];

        float dx = pi.x - pj.x;
        float dy = pi.y - pj.y;
        float a  = fmaf(dy, pi.w, dx * pi.z);     // base . h_i
        float b  = fmaf(dy, pj.w, dx * pj.z);     // base . h_j
        float g  = fmaf(pi.w, pj.w, pi.z * pj.z); // h_i . h_j
        float B  = fmaf(dy, dy, dx * dx);
        float a2 = a + a;
        float nb2 = -(b + b);
        float ng2 = -(g + g);

        float d2c[NC];
        #pragma unroll
        for (int c = 0; c < NC; c++) {
            float x  = fmaf((float)c, di, si0);   // i circle offset
            float u  = fmaf(x, x + a2, B);        // B + x^2 + 2ax
            float ws = fmaf(g, x, b);             // continuous argmin over w
            float yn = fmaf(ws, idj, offj);       // grid coordinate of w*
            float r  = __fadd_rn(yn, MAGIC);      // round-to-nearest-int
            r        = __fadd_rn(r, -MAGIC);
            r        = fminf(fmaxf(r, 0.0f), 4.0f);   // clamp to segment
            float wv = fmaf(r, dj, sj0);          // nearest j circle offset
            float tm = fmaf(ng2, x, nb2);         // -2b - 2gx
            d2c[c]   = fmaf(wv, wv + tm, u);      // exact min over d for this c
        }
        float m = fminf(fminf(fminf(d2c[0], d2c[1]), fminf(d2c[2], d2c[3])), d2c[4]);

        float md = sqrtf(fmaxf(m, 0.0f));
        float pd = pen[ig * NA + jg];
        float pv = 1.0f - __fdividef(md, pd);
        const unsigned idx = ((unsigned)t * NA + ig) * NA + jg;
        out[idx] = pv;
        if (write_mask)
            out[P + idx] = (pv >= 0.0f && ig != jg) ? 1.0f : 0.0f;
        sTile[il][jl] = pv;
    }

    // ---- Transposed write for off-diagonal tile pairs ----
    if (it != jt) {
        __syncthreads();
        #pragma unroll
        for (int q = 0; q < (TILE * TILE) / NTHREADS; ++q) {
            int e  = tid + q * NTHREADS;
            int jj = e >> 5;
            int ii = e & 31;
            float pv = sTile[ii][jj];             // stride-33: conflict-free
            const unsigned idxT = ((unsigned)t * NA + jt * TILE + jj) * NA + it * TILE + ii;
            out[idxT] = pv;
            if (write_mask)
                out[P + idxT] = (pv >= 0.0f) ? 1.0f : 0.0f;  // it!=jt: never diagonal
        }
    }
}

extern "C" void kernel_launch(void* const* d_in, const int* in_sizes, int n_in,
                              void* d_out, int out_size) {
    const float* traj      = (const float*)d_in[0];
    const float* centroids = (const float*)d_in[1];
    const float* pen       = (const float*)d_in[2];
    // d_in[3] = off_diag_mask (~eye) — recomputed as (i != j) on device.

    float* out = (float*)d_out;
    const size_t P = (size_t)TT * NA * NA;
    int write_mask = ((size_t)out_size >= 2 * P) ? 1 : 0;

    dim3 grid(TT, NPAIRS);   // (80, 21) = 1680 blocks
    veh_coll_kernel<<<grid, NTHREADS>>>(traj, centroids, pen, out, write_mask);
}

// round 12
// speedup vs baseline: 1.4723x; 1.0266x over previous
#include <cuda_runtime.h>
#include <cstddef>

#define NA 192
#define TT 80
#define NC 5
#define TILE 32
#define HTILE 16
#define NTHREADS 256
#define NPAIRS 21
#define MAGIC 12582912.0f   // 1.5 * 2^23: add/sub rounds to nearest int

__constant__ unsigned char cIT[NPAIRS] = {0,0,0,0,0,0,1,1,1,1,1,2,2,2,2,3,3,3,4,4,5};
__constant__ unsigned char cJT[NPAIRS] = {0,1,2,3,4,5,1,2,3,4,5,2,3,4,5,3,4,5,4,5,5};

__global__ __launch_bounds__(NTHREADS) void veh_coll_kernel(
    const float* __restrict__ traj,        // (NA, T, 4)
    const float* __restrict__ centroids,   // (NA, NC, 4)
    const float* __restrict__ pen,         // (NA, NA)
    float* __restrict__ out,               // [pen (T,NA,NA)][mask (T,NA,NA)]
    int write_mask)
{
    __shared__ float4 sPose[2 * TILE];         // [0,32) = I tile, [32,64) = J tile
    __shared__ float  sG0[2 * TILE];           // s_0
    __shared__ float  sGd[2 * TILE];           // delta
    __shared__ float  sGi[2 * TILE];           // 1/delta
    __shared__ float  sTile[HTILE][TILE + 2];  // pv staged for transpose (stride 34)

    const int t    = blockIdx.x;
    const int pr2  = blockIdx.y;
    const int pr   = pr2 >> 1;
    const int ih   = (pr2 & 1) * HTILE;        // i half-offset within tile
    const int it   = cIT[pr];
    const int jt   = cJT[pr];
    const int tid  = threadIdx.x;

    // ---- Stage per-agent pose + uniform circle-grid parameters (both tiles) ----
    if (tid < 2 * TILE) {
        int side = tid >> 5, loc = tid & 31;
        int a = (side ? jt : it) * TILE + loc;
        float4 tr = *reinterpret_cast<const float4*>(traj + (a * TT + t) * 4);
        float inv = rsqrtf(tr.z * tr.z + tr.w * tr.w);
        sPose[tid] = make_float4(tr.x, tr.y, tr.z * inv, tr.w * inv);
        float s0 = centroids[(a * NC + 0) * 4];
        float s4 = centroids[(a * NC + 4) * 4];
        float dd = (s4 - s0) * 0.25f;          // uniform spacing (linspace frac)
        sG0[tid] = s0;
        sGd[tid] = dd;
        sGi[tid] = __frcp_rn(dd);
    }
    __syncthreads();

    // ---- lane = j local; each warp walks 2 i's of this half-tile ----
    const int jl   = tid & 31;
    const int warp = tid >> 5;
    const int jg   = jt * TILE + jl;

    const float4 pj   = sPose[TILE + jl];
    const float  sj0  = sG0[TILE + jl];
    const float  dj   = sGd[TILE + jl];
    const float  idj  = sGi[TILE + jl];
    const float  offj = -sj0 * idj;

    const unsigned P = (unsigned)TT * NA * NA;

    #pragma unroll
    for (int w = 0; w < HTILE / (NTHREADS / 32); ++w) {
        const int il = ih + warp + w * (NTHREADS / 32);
        const int ig = it * TILE + il;

        const float4 pi = sPose[il];           // broadcast
        const float si0 = sG0[il];
        const float di  = sGd[il];

        float dx = pi.x - pj.x;
        float dy = pi.y - pj.y;
        float a  = fmaf(dy, pi.w, dx * pi.z);     // base . h_i
        float b  = fmaf(dy, pj.w, dx * pj.z);     // base . h_j
        float g  = fmaf(pi.w, pj.w, pi.z * pj.z); // h_i . h_j
        float B  = fmaf(dy, dy, dx * dx);
        float a2  = a + a;
        float nb2 = -(b + b);
        float ng2 = -(g + g);
        float gi  = g * idj;                      // hoisted: yn = x*gi + byn
        float byn = fmaf(b, idj, offj);

        float d2c[NC];
        #pragma unroll
        for (int c = 0; c < NC; c++) {
            float x  = fmaf((float)c, di, si0);   // i circle offset
            float yn = fmaf(x, gi, byn);          // grid coord of w* = b + g x
            float r  = fminf(fmaxf(yn, 0.0f), 4.0f);
            r        = __fadd_rn(r, MAGIC);       // round-to-nearest-int
            r        = __fadd_rn(r, -MAGIC);
            float wv = fmaf(r, dj, sj0);          // nearest j circle offset
            float u  = fmaf(x, x + a2, B);        // B + x^2 + 2ax
            float tm = fmaf(ng2, x, nb2);         // -2b - 2gx
            d2c[c]   = fmaf(wv, wv + tm, u);      // exact min over d for this c
        }
        float m = fminf(fminf(fminf(d2c[0], d2c[1]), fminf(d2c[2], d2c[3])), d2c[4]);

        float md = sqrtf(fmaxf(m, 0.0f));
        float pd = pen[ig * NA + jg];
        float pv = 1.0f - __fdividef(md, pd);
        const unsigned idx = ((unsigned)t * NA + ig) * NA + jg;
        out[idx] = pv;
        if (write_mask)
            out[P + idx] = (pv >= 0.0f && ig != jg) ? 1.0f : 0.0f;
        sTile[il - ih][jl] = pv;
    }

    // ---- Transposed write for off-diagonal tile pairs ----
    if (it != jt) {
        __syncthreads();
        #pragma unroll
        for (int q = 0; q < (HTILE * TILE) / NTHREADS; ++q) {
            int e  = tid + q * NTHREADS;
            int jj = e >> 4;                      // 0..31 (j index)
            int ii = e & 15;                      // 0..15 (i within half)
            float pv = sTile[ii][jj];             // stride 34: conflict-free
            const unsigned idxT =
                ((unsigned)t * NA + jt * TILE + jj) * NA + it * TILE + ih + ii;
            out[idxT] = pv;
            if (write_mask)
                out[P + idxT] = (pv >= 0.0f) ? 1.0f : 0.0f;  // it!=jt: off-diagonal
        }
    }
}

extern "C" void kernel_launch(void* const* d_in, const int* in_sizes, int n_in,
                              void* d_out, int out_size) {
    const float* traj      = (const float*)d_in[0];
    const float* centroids = (const float*)d_in[1];
    const float* pen       = (const float*)d_in[2];
    // d_in[3] = off_diag_mask (~eye) — recomputed as (i != j) on device.

    float* out = (float*)d_out;
    const size_t P = (size_t)TT * NA * NA;
    int write_mask = ((size_t)out_size >= 2 * P) ? 1 : 0;

    dim3 grid(TT, NPAIRS * 2);   // (80, 42) = 3360 half-tile blocks
    veh_coll_kernel<<<grid, NTHREADS>>>(traj, centroids, pen, out, write_mask);
}